// round 2
// baseline (speedup 1.0000x reference)
#include <cuda_runtime.h>
#include <cstdint>

#define N_SITES 200000
#define C 128
#define NOFF 27
#define TOTAL (N_SITES * C)         // 25,600,000 floats
#define TOTAL4 (TOTAL / 4)          // 6,400,000 float4
#define PAIRS_TILE 64
#define NCHUNK (N_SITES / PAIRS_TILE)   // 3125 (exact)
#define STATS_ROWS 512
#define NB_STATS ((N_SITES + STATS_ROWS - 1) / STATS_ROWS)  // 391
#define EPS 1e-4f

// ---------------- scratch (device globals; no allocations allowed) ----------
__device__ float g_buf1[TOTAL];
__device__ float g_buf2[TOTAL];
__device__ float g_part[NB_STATS * C * 2];
__device__ float g_scale[C];
__device__ float g_bias[C];

// ---------------- packed fp32x2 helpers -------------------------------------
__device__ __forceinline__ unsigned long long fma2(unsigned long long a,
                                                   unsigned long long b,
                                                   unsigned long long c) {
    unsigned long long d;
    asm("fma.rn.f32x2 %0, %1, %2, %3;" : "=l"(d) : "l"(a), "l"(b), "l"(c));
    return d;
}

__device__ __forceinline__ unsigned long long pack2(float f) {
    unsigned long long d;
    unsigned u = __float_as_uint(f);
    asm("mov.b64 %0, {%1, %1};" : "=l"(d) : "r"(u));
    return d;
}

__device__ __forceinline__ float2 unpack2(unsigned long long v) {
    unsigned lo, hi;
    asm("mov.b64 {%0, %1}, %2;" : "=r"(lo), "=r"(hi) : "l"(v));
    return make_float2(__uint_as_float(lo), __uint_as_float(hi));
}

__device__ __forceinline__ void red_add4(float* p, float a, float b, float c, float d) {
    asm volatile("red.global.add.v4.f32 [%0], {%1, %2, %3, %4};"
                 :: "l"(p), "f"(a), "f"(b), "f"(c), "f"(d) : "memory");
}

// ---------------- zero accumulator ------------------------------------------
__global__ void __launch_bounds__(256) zero_kernel(float4* __restrict__ p) {
    int i = blockIdx.x * 256 + threadIdx.x;
    if (i < TOTAL4) p[i] = make_float4(0.f, 0.f, 0.f, 0.f);
}

// ---------------- pair-list conv: out[oi] += feats[ii] @ W[k] ----------------
// grid = (NCHUNK, 27). Block: 256 threads = 8 warps.
// Tile: 64 pairs x 128 out-channels. warp w owns rows {w, w+8, ..., w+56},
// lane l owns out-channels [4l, 4l+4). Valid pairs are a prefix of each offset
// row (padding value == N_SITES), so a chunk whose first entry is dummy exits.
__global__ void __launch_bounds__(256, 4) conv_pairs_kernel(
    const float* __restrict__ feats, const float* __restrict__ W,
    const int* __restrict__ in_idx, const int* __restrict__ out_idx,
    float* __restrict__ out)
{
    __shared__ float4 f_s[PAIRS_TILE * 32];  // 64 rows x 128 ch (32 KB)
    __shared__ float4 w_s[32 * 32];          // 32 j x 128 c (16 KB)
    __shared__ int s_ii[PAIRS_TILE];
    __shared__ int s_oi[PAIRS_TILE];

    const int k = blockIdx.y;
    const long base = (long)blockIdx.x * PAIRS_TILE;
    const int* ik = in_idx + (long)k * N_SITES;
    if (__ldg(&ik[base]) >= N_SITES) return;  // fully-padded chunk
    const int* ok = out_idx + (long)k * N_SITES;

    const int tid = threadIdx.x;
    if (tid < PAIRS_TILE) {
        s_ii[tid] = __ldg(&ik[base + tid]);
        s_oi[tid] = __ldg(&ok[base + tid]);
    }
    __syncthreads();

    // gather features (dummy rows -> zeros)
    const float4* f4 = (const float4*)feats;
    #pragma unroll
    for (int idx = tid; idx < PAIRS_TILE * 32; idx += 256) {
        int ii = s_ii[idx >> 5];
        f_s[idx] = (ii < N_SITES) ? __ldg(&f4[(long)ii * 32 + (idx & 31)])
                                  : make_float4(0.f, 0.f, 0.f, 0.f);
    }

    const int warp = tid >> 5;
    const int lane = tid & 31;
    unsigned long long acc[8][2];
    #pragma unroll
    for (int rl = 0; rl < 8; rl++) { acc[rl][0] = 0ull; acc[rl][1] = 0ull; }

    const float4* W4 = (const float4*)W + (long)k * (C * C / 4);
    const float* f_sf = (const float*)f_s;

    for (int jc = 0; jc < 4; jc++) {
        __syncthreads();  // covers gather (jc=0) and previous w_s reads
        #pragma unroll
        for (int idx = tid; idx < 1024; idx += 256)
            w_s[idx] = __ldg(&W4[(jc * 32 + (idx >> 5)) * 32 + (idx & 31)]);
        __syncthreads();
        #pragma unroll
        for (int j = 0; j < 32; j++) {
            ulonglong2 wv = *reinterpret_cast<const ulonglong2*>(&w_s[j * 32 + lane]);
            const int jg = jc * 32 + j;
            #pragma unroll
            for (int rl = 0; rl < 8; rl++) {
                unsigned long long ff = pack2(f_sf[(warp + rl * 8) * C + jg]);
                acc[rl][0] = fma2(ff, wv.x, acc[rl][0]);
                acc[rl][1] = fma2(ff, wv.y, acc[rl][1]);
            }
        }
    }

    #pragma unroll
    for (int rl = 0; rl < 8; rl++) {
        const int oi = s_oi[warp + rl * 8];
        if (oi < N_SITES) {
            float2 a = unpack2(acc[rl][0]);
            float2 b = unpack2(acc[rl][1]);
            red_add4(out + (long)oi * C + lane * 4, a.x, a.y, b.x, b.y);
        }
    }
}

// ---------------- BN stats: per-block partial sum / sumsq per channel -------
__global__ void __launch_bounds__(256) bn_stats_kernel(const float* __restrict__ x) {
    const int b = blockIdx.x;
    const int r0 = b * STATS_ROWS;
    const int r1 = min(r0 + STATS_ROWS, N_SITES);
    const int c = threadIdx.x & 127;
    const int half = threadIdx.x >> 7;

    float s = 0.f, ss = 0.f;
    for (int r = r0 + half; r < r1; r += 2) {
        float v = __ldg(&x[(long)r * C + c]);
        s += v;
        ss += v * v;
    }
    __shared__ float sm[512];
    sm[threadIdx.x] = s;
    sm[256 + threadIdx.x] = ss;
    __syncthreads();
    if (half == 0) {
        g_part[((long)b * C + c) * 2 + 0] = s + sm[threadIdx.x + 128];
        g_part[((long)b * C + c) * 2 + 1] = ss + sm[256 + threadIdx.x + 128];
    }
}

// fixed-order finalize: deterministic mean/var -> fused scale/bias
__global__ void bn_final_kernel(const float* __restrict__ gamma,
                                const float* __restrict__ beta) {
    const int c = threadIdx.x;
    float s = 0.f, ss = 0.f;
    for (int b = 0; b < NB_STATS; b++) {
        s  += g_part[((long)b * C + c) * 2 + 0];
        ss += g_part[((long)b * C + c) * 2 + 1];
    }
    const float inv_n = 1.f / (float)N_SITES;
    float m = s * inv_n;
    float v = ss * inv_n - m * m;
    float sc = gamma[c] * rsqrtf(v + EPS);
    g_scale[c] = sc;
    g_bias[c] = beta[c] - m * sc;
}

// ---------------- elementwise: in-place BN + ReLU ---------------------------
__global__ void __launch_bounds__(256) bn_relu_kernel(float* __restrict__ x) {
    int i = blockIdx.x * 256 + threadIdx.x;
    if (i >= TOTAL4) return;
    float4 v = ((const float4*)x)[i];
    int c4 = i & 31;
    float4 s = ((const float4*)g_scale)[c4];
    float4 b = ((const float4*)g_bias)[c4];
    float4 o;
    o.x = fmaxf(fmaf(v.x, s.x, b.x), 0.f);
    o.y = fmaxf(fmaf(v.y, s.y, b.y), 0.f);
    o.z = fmaxf(fmaf(v.z, s.z, b.z), 0.f);
    o.w = fmaxf(fmaf(v.w, s.w, b.w), 0.f);
    ((float4*)x)[i] = o;
}

// ---------------- elementwise: BN + residual + ReLU -> output ---------------
__global__ void __launch_bounds__(256) apply_res_kernel(
    const float* __restrict__ x, const float* __restrict__ feats,
    float* __restrict__ out)
{
    int i = blockIdx.x * 256 + threadIdx.x;
    if (i >= TOTAL4) return;
    float4 v = ((const float4*)x)[i];
    float4 f = ((const float4*)feats)[i];
    int c4 = i & 31;
    float4 s = ((const float4*)g_scale)[c4];
    float4 b = ((const float4*)g_bias)[c4];
    float4 o;
    o.x = fmaxf(fmaf(v.x, s.x, b.x) + f.x, 0.f);
    o.y = fmaxf(fmaf(v.y, s.y, b.y) + f.y, 0.f);
    o.z = fmaxf(fmaf(v.z, s.z, b.z) + f.z, 0.f);
    o.w = fmaxf(fmaf(v.w, s.w, b.w) + f.w, 0.f);
    ((float4*)out)[i] = o;
}

// ---------------- launch ----------------------------------------------------
extern "C" void kernel_launch(void* const* d_in, const int* in_sizes, int n_in,
                              void* d_out, int out_size) {
    const float* feats  = (const float*)d_in[0];
    const float* W1     = (const float*)d_in[1];
    const float* gamma1 = (const float*)d_in[2];
    const float* beta1  = (const float*)d_in[3];
    const float* W2     = (const float*)d_in[4];
    const float* gamma2 = (const float*)d_in[5];
    const float* beta2  = (const float*)d_in[6];
    const int*   iidx   = (const int*)d_in[7];
    const int*   oidx   = (const int*)d_in[8];
    float* out = (float*)d_out;

    void *pb1, *pb2;
    cudaGetSymbolAddress(&pb1, g_buf1);
    cudaGetSymbolAddress(&pb2, g_buf2);
    float* buf1 = (float*)pb1;
    float* buf2 = (float*)pb2;

    const int EB = (TOTAL4 + 255) / 256;  // elementwise grid
    dim3 cg(NCHUNK, NOFF);

    // conv1 -> BN1 -> ReLU
    zero_kernel<<<EB, 256>>>((float4*)buf1);
    conv_pairs_kernel<<<cg, 256>>>(feats, W1, iidx, oidx, buf1);
    bn_stats_kernel<<<NB_STATS, 256>>>(buf1);
    bn_final_kernel<<<1, C>>>(gamma1, beta1);
    bn_relu_kernel<<<EB, 256>>>(buf1);

    // conv2 -> BN2 -> +residual -> ReLU
    zero_kernel<<<EB, 256>>>((float4*)buf2);
    conv_pairs_kernel<<<cg, 256>>>(buf1, W2, iidx, oidx, buf2);
    bn_stats_kernel<<<NB_STATS, 256>>>(buf2);
    bn_final_kernel<<<1, C>>>(gamma2, beta2);
    apply_res_kernel<<<EB, 256>>>(buf2, feats, out);
}

// round 5
// speedup vs baseline: 1.6840x; 1.6840x over previous
#include <cuda_runtime.h>
#include <cstdint>

#define N_SITES 200000
#define C 128
#define NOFF 27
#define TOTAL (N_SITES * C)
#define TOTAL4 (TOTAL / 4)
#define TILE_M 128
#define NCHUNK ((N_SITES + TILE_M - 1) / TILE_M)   // 1563
#define STATS_ROWS 512
#define NB_STATS ((N_SITES + STATS_ROWS - 1) / STATS_ROWS)  // 391
#define EPS 1e-4f
#define W_ELEMS (NOFF * C * C)

// smem tile strides (floats); 36 % 32 == 4 -> conflict-free frag loads
#define LDS_STRIDE 36

// ---------------- scratch (device globals; no allocations allowed) ----------
__device__ float g_buf1[TOTAL];
__device__ float g_buf2[TOTAL];
__device__ float g_wt1[W_ELEMS];   // W transposed to [27][co][ci], tf32-rounded
__device__ float g_wt2[W_ELEMS];
__device__ float g_part[NB_STATS * C * 2];
__device__ float g_scale[C];
__device__ float g_bias[C];

// ---------------- helpers ----------------------------------------------------
__device__ __forceinline__ float rna_tf32(float x) {
    float r;
    asm("cvt.rna.tf32.f32 %0, %1;" : "=f"(r) : "f"(x));
    return r;
}
__device__ __forceinline__ void red_add2(float* p, float a, float b) {
    asm volatile("red.global.add.v2.f32 [%0], {%1, %2};"
                 :: "l"(p), "f"(a), "f"(b) : "memory");
}
__device__ __forceinline__ void mma_tf32(float* d, const uint32_t* a, const uint32_t* b) {
    asm volatile(
        "mma.sync.aligned.m16n8k8.row.col.f32.tf32.tf32.f32 "
        "{%0,%1,%2,%3}, {%4,%5,%6,%7}, {%8,%9}, {%0,%1,%2,%3};"
        : "+f"(d[0]), "+f"(d[1]), "+f"(d[2]), "+f"(d[3])
        : "r"(a[0]), "r"(a[1]), "r"(a[2]), "r"(a[3]), "r"(b[0]), "r"(b[1]));
}

// ---------------- prep: transpose W[k][ci][co] -> Wt[k][co][ci], rna round --
__global__ void __launch_bounds__(256) prep_w_kernel(const float* __restrict__ W,
                                                     float* __restrict__ Wt) {
    const int k = blockIdx.y;
    const int idx = blockIdx.x * 256 + threadIdx.x;  // over 16384
    const int ci = idx >> 7;
    const int co = idx & 127;
    float v = __ldg(&W[(long)k * 16384 + ci * 128 + co]);  // coalesced read
    Wt[(long)k * 16384 + co * 128 + ci] = rna_tf32(v);
}

// ---------------- zero accumulator ------------------------------------------
__global__ void __launch_bounds__(256) zero_kernel(float4* __restrict__ p) {
    int i = blockIdx.x * 256 + threadIdx.x;
    if (i < TOTAL4) p[i] = make_float4(0.f, 0.f, 0.f, 0.f);
}

// ---------------- tf32 mma.sync pair-tile conv -------------------------------
// grid = (NCHUNK, 27), block = 256 (8 warps: 4 M-blocks x 2 N-blocks).
// Tile: 128 pairs x 128 outch x K=128, chunked K by 32.
// D[m,n] = sum_k A[m,k] * Wt[n,k]  (mma row.col: A row-major, B "col-major" = n-rows k-major)
__global__ void __launch_bounds__(256, 2) conv_mma_kernel(
    const float* __restrict__ feats, const float* __restrict__ Wt,
    const int* __restrict__ in_idx, const int* __restrict__ out_idx,
    float* __restrict__ out)
{
    __shared__ float As[TILE_M * LDS_STRIDE];   // 128 x 32 (+pad)
    __shared__ float Bs[C * LDS_STRIDE];        // 128 x 32 (+pad)
    __shared__ int s_ii[TILE_M];
    __shared__ int s_oi[TILE_M];

    const int k = blockIdx.y;
    const long base = (long)blockIdx.x * TILE_M;
    const int* ik = in_idx + (long)k * N_SITES;
    if (__ldg(&ik[base]) >= N_SITES) return;  // fully-padded chunk (valid prefix)
    const int* ok = out_idx + (long)k * N_SITES;

    const int tid = threadIdx.x;
    const int wid = tid >> 5;
    const int lane = tid & 31;
    const int g = lane >> 2;       // group id (row within frag)
    const int tig = lane & 3;      // thread in group

    if (tid < TILE_M) {
        long p = base + tid;
        bool v = (p < N_SITES);
        s_ii[tid] = v ? __ldg(&ik[p]) : N_SITES;
        s_oi[tid] = v ? __ldg(&ok[p]) : N_SITES;
    }

    const int warp_m = wid & 3;    // 0..3 -> 32-row band
    const int warp_n = wid >> 2;   // 0..1 -> 64-col band
    const int m0 = warp_m * 32;
    const int n0 = warp_n * 64;

    float acc[2][8][4];
    #pragma unroll
    for (int mf = 0; mf < 2; mf++)
        #pragma unroll
        for (int nf = 0; nf < 8; nf++)
            #pragma unroll
            for (int r = 0; r < 4; r++) acc[mf][nf][r] = 0.f;

    const float4* f4 = (const float4*)feats;
    const float4* w4 = (const float4*)(Wt + (long)k * 16384);
    const int r_st = tid >> 3;          // staging row (two rows per 8 iter-steps)
    const int g4 = tid & 7;             // granule within 32-float chunk-row

    for (int kc = 0; kc < 4; kc++) {
        __syncthreads();   // protect previous chunk reads (and s_ii on kc=0)
        // stage A: 128 rows x 8 float4 granules = 1024; 4 per thread
        #pragma unroll
        for (int it = 0; it < 4; it++) {
            int r = r_st + it * 32;
            int ii = s_ii[r];
            float4 v = (ii < N_SITES) ? __ldg(&f4[(long)ii * 32 + kc * 8 + g4])
                                      : make_float4(0.f, 0.f, 0.f, 0.f);
            v.x = rna_tf32(v.x); v.y = rna_tf32(v.y);
            v.z = rna_tf32(v.z); v.w = rna_tf32(v.w);
            *(float4*)&As[r * LDS_STRIDE + g4 * 4] = v;
        }
        // stage B (already tf32-rounded)
        #pragma unroll
        for (int it = 0; it < 4; it++) {
            int r = r_st + it * 32;
            *(float4*)&Bs[r * LDS_STRIDE + g4 * 4] = __ldg(&w4[r * 32 + kc * 8 + g4]);
        }
        __syncthreads();

        #pragma unroll
        for (int ks = 0; ks < 4; ks++) {
            const int kk = ks * 8;
            uint32_t b[8][2];
            #pragma unroll
            for (int nf = 0; nf < 8; nf++) {
                const int n = n0 + nf * 8 + g;
                b[nf][0] = __float_as_uint(Bs[n * LDS_STRIDE + kk + tig]);
                b[nf][1] = __float_as_uint(Bs[n * LDS_STRIDE + kk + tig + 4]);
            }
            #pragma unroll
            for (int mf = 0; mf < 2; mf++) {
                const int row = m0 + mf * 16 + g;
                uint32_t a[4];
                a[0] = __float_as_uint(As[row * LDS_STRIDE + kk + tig]);
                a[1] = __float_as_uint(As[(row + 8) * LDS_STRIDE + kk + tig]);
                a[2] = __float_as_uint(As[row * LDS_STRIDE + kk + tig + 4]);
                a[3] = __float_as_uint(As[(row + 8) * LDS_STRIDE + kk + tig + 4]);
                #pragma unroll
                for (int nf = 0; nf < 8; nf++)
                    mma_tf32(acc[mf][nf], a, b[nf]);
            }
        }
    }

    // ---- epilogue: scatter-add rows to out[oi] -------------------------------
    #pragma unroll
    for (int mf = 0; mf < 2; mf++) {
        const int r_lo = m0 + mf * 16 + g;
        const int oi_lo = s_oi[r_lo];
        const int oi_hi = s_oi[r_lo + 8];
        #pragma unroll
        for (int nf = 0; nf < 8; nf++) {
            const int col = n0 + nf * 8 + 2 * tig;
            if (oi_lo < N_SITES)
                red_add2(out + (long)oi_lo * C + col, acc[mf][nf][0], acc[mf][nf][1]);
            if (oi_hi < N_SITES)
                red_add2(out + (long)oi_hi * C + col, acc[mf][nf][2], acc[mf][nf][3]);
        }
    }
}

// ---------------- BN stats: per-block partial sum / sumsq per channel -------
__global__ void __launch_bounds__(256) bn_stats_kernel(const float* __restrict__ x) {
    const int b = blockIdx.x;
    const int r0 = b * STATS_ROWS;
    const int r1 = min(r0 + STATS_ROWS, N_SITES);
    const int c = threadIdx.x & 127;
    const int half = threadIdx.x >> 7;

    float s = 0.f, ss = 0.f;
    for (int r = r0 + half; r < r1; r += 2) {
        float v = __ldg(&x[(long)r * C + c]);
        s += v;
        ss += v * v;
    }
    __shared__ float sm[512];
    sm[threadIdx.x] = s;
    sm[256 + threadIdx.x] = ss;
    __syncthreads();
    if (half == 0) {
        g_part[((long)b * C + c) * 2 + 0] = s + sm[threadIdx.x + 128];
        g_part[((long)b * C + c) * 2 + 1] = ss + sm[256 + threadIdx.x + 128];
    }
}

// fixed-order finalize (4 workers per channel): deterministic mean/var
__global__ void __launch_bounds__(512) bn_final_kernel(const float* __restrict__ gamma,
                                                       const float* __restrict__ beta) {
    const int c = threadIdx.x & 127;
    const int w = threadIdx.x >> 7;  // 0..3
    float s = 0.f, ss = 0.f;
    for (int b = w; b < NB_STATS; b += 4) {
        s  += g_part[((long)b * C + c) * 2 + 0];
        ss += g_part[((long)b * C + c) * 2 + 1];
    }
    __shared__ float sm[1024];
    sm[threadIdx.x] = s;
    sm[512 + threadIdx.x] = ss;
    __syncthreads();
    if (w == 0) {
        #pragma unroll
        for (int j = 1; j < 4; j++) {
            s  += sm[j * 128 + c];
            ss += sm[512 + j * 128 + c];
        }
        const float inv_n = 1.f / (float)N_SITES;
        float m = s * inv_n;
        float v = ss * inv_n - m * m;
        float sc = gamma[c] * rsqrtf(v + EPS);
        g_scale[c] = sc;
        g_bias[c] = beta[c] - m * sc;
    }
}

// ---------------- elementwise: in-place BN + ReLU ---------------------------
__global__ void __launch_bounds__(256) bn_relu_kernel(float* __restrict__ x) {
    int i = blockIdx.x * 256 + threadIdx.x;
    if (i >= TOTAL4) return;
    float4 v = ((const float4*)x)[i];
    int c4 = i & 31;
    float4 s = ((const float4*)g_scale)[c4];
    float4 b = ((const float4*)g_bias)[c4];
    float4 o;
    o.x = fmaxf(fmaf(v.x, s.x, b.x), 0.f);
    o.y = fmaxf(fmaf(v.y, s.y, b.y), 0.f);
    o.z = fmaxf(fmaf(v.z, s.z, b.z), 0.f);
    o.w = fmaxf(fmaf(v.w, s.w, b.w), 0.f);
    ((float4*)x)[i] = o;
}

// ---------------- elementwise: BN + residual + ReLU -> output ---------------
__global__ void __launch_bounds__(256) apply_res_kernel(
    const float* __restrict__ x, const float* __restrict__ feats,
    float* __restrict__ out)
{
    int i = blockIdx.x * 256 + threadIdx.x;
    if (i >= TOTAL4) return;
    float4 v = ((const float4*)x)[i];
    float4 f = ((const float4*)feats)[i];
    int c4 = i & 31;
    float4 s = ((const float4*)g_scale)[c4];
    float4 b = ((const float4*)g_bias)[c4];
    float4 o;
    o.x = fmaxf(fmaf(v.x, s.x, b.x) + f.x, 0.f);
    o.y = fmaxf(fmaf(v.y, s.y, b.y) + f.y, 0.f);
    o.z = fmaxf(fmaf(v.z, s.z, b.z) + f.z, 0.f);
    o.w = fmaxf(fmaf(v.w, s.w, b.w) + f.w, 0.f);
    ((float4*)out)[i] = o;
}

// ---------------- launch ----------------------------------------------------
extern "C" void kernel_launch(void* const* d_in, const int* in_sizes, int n_in,
                              void* d_out, int out_size) {
    const float* feats  = (const float*)d_in[0];
    const float* W1     = (const float*)d_in[1];
    const float* gamma1 = (const float*)d_in[2];
    const float* beta1  = (const float*)d_in[3];
    const float* W2     = (const float*)d_in[4];
    const float* gamma2 = (const float*)d_in[5];
    const float* beta2  = (const float*)d_in[6];
    const int*   iidx   = (const int*)d_in[7];
    const int*   oidx   = (const int*)d_in[8];
    float* out = (float*)d_out;

    void *pb1, *pb2, *pw1, *pw2;
    cudaGetSymbolAddress(&pb1, g_buf1);
    cudaGetSymbolAddress(&pb2, g_buf2);
    cudaGetSymbolAddress(&pw1, g_wt1);
    cudaGetSymbolAddress(&pw2, g_wt2);
    float* buf1 = (float*)pb1;
    float* buf2 = (float*)pb2;
    float* wt1  = (float*)pw1;
    float* wt2  = (float*)pw2;

    const int EB = (TOTAL4 + 255) / 256;
    dim3 cg(NCHUNK, NOFF);
    dim3 pg(64, NOFF);  // prep_w: 64*256 = 16384 elems per k

    // weight transpose + tf32 rounding
    prep_w_kernel<<<pg, 256>>>(W1, wt1);
    prep_w_kernel<<<pg, 256>>>(W2, wt2);

    // conv1 -> BN1 -> ReLU
    zero_kernel<<<EB, 256>>>((float4*)buf1);
    conv_mma_kernel<<<cg, 256>>>(feats, wt1, iidx, oidx, buf1);
    bn_stats_kernel<<<NB_STATS, 256>>>(buf1);
    bn_final_kernel<<<1, 512>>>(gamma1, beta1);
    bn_relu_kernel<<<EB, 256>>>(buf1);

    // conv2 -> BN2 -> +residual -> ReLU
    zero_kernel<<<EB, 256>>>((float4*)buf2);
    conv_mma_kernel<<<cg, 256>>>(buf1, wt2, iidx, oidx, buf2);
    bn_stats_kernel<<<NB_STATS, 256>>>(buf2);
    bn_final_kernel<<<1, 512>>>(gamma2, beta2);
    apply_res_kernel<<<EB, 256>>>(buf2, feats, out);
}

// round 6
// speedup vs baseline: 2.5474x; 1.5128x over previous
#include <cuda_runtime.h>
#include <cstdint>

#define N_SITES 200000
#define C 128
#define NOFF 27
#define TOTAL (N_SITES * C)
#define TOTAL4 (TOTAL / 4)
#define TILE_M 128
#define NCHUNK ((N_SITES + TILE_M - 1) / TILE_M)   // 1563
#define STATS_ROWS 512
#define NB_STATS ((N_SITES + STATS_ROWS - 1) / STATS_ROWS)  // 391
#define EPS 1e-4f
#define W_ELEMS (NOFF * C * C)

// smem tile strides (floats); 36 % 32 == 4 -> conflict-free frag loads
#define LDS_STRIDE 36
#define BUF_FLOATS (2 * TILE_M * LDS_STRIDE)   // A + B per stage buffer = 9216
#define SMEM_DYN_BYTES (2 * BUF_FLOATS * 4)    // 73728

// ---------------- scratch (device globals; no allocations allowed) ----------
__device__ float g_buf1[TOTAL];
__device__ float g_buf2[TOTAL];
__device__ float g_wt1[W_ELEMS];   // W transposed to [27][co][ci], tf32-rounded
__device__ float g_wt2[W_ELEMS];
__device__ float g_part[NB_STATS * C * 2];
__device__ float g_scale[C];
__device__ float g_bias[C];

// ---------------- helpers ----------------------------------------------------
__device__ __forceinline__ uint32_t smem_u32(const void* p) {
    uint32_t a;
    asm("{ .reg .u64 t; cvta.to.shared.u64 t, %1; cvt.u32.u64 %0, t; }" : "=r"(a) : "l"(p));
    return a;
}
__device__ __forceinline__ float rna_tf32(float x) {
    float r;
    asm("cvt.rna.tf32.f32 %0, %1;" : "=f"(r) : "f"(x));
    return r;
}
__device__ __forceinline__ void red_add2(float* p, float a, float b) {
    asm volatile("red.global.add.v2.f32 [%0], {%1, %2};"
                 :: "l"(p), "f"(a), "f"(b) : "memory");
}
__device__ __forceinline__ void st2(float* p, float a, float b) {
    asm volatile("st.global.v2.f32 [%0], {%1, %2};"
                 :: "l"(p), "f"(a), "f"(b) : "memory");
}
__device__ __forceinline__ void cp_async16(uint32_t dst, const void* src, int src_bytes) {
    asm volatile("cp.async.ca.shared.global [%0], [%1], 16, %2;"
                 :: "r"(dst), "l"(src), "r"(src_bytes) : "memory");
}
#define CP_COMMIT() asm volatile("cp.async.commit_group;" ::: "memory")
#define CP_WAIT(n)  asm volatile("cp.async.wait_group %0;" :: "n"(n) : "memory")

__device__ __forceinline__ void mma_tf32(float* d, const uint32_t* a, const uint32_t* b) {
    asm volatile(
        "mma.sync.aligned.m16n8k8.row.col.f32.tf32.tf32.f32 "
        "{%0,%1,%2,%3}, {%4,%5,%6,%7}, {%8,%9}, {%0,%1,%2,%3};"
        : "+f"(d[0]), "+f"(d[1]), "+f"(d[2]), "+f"(d[3])
        : "r"(a[0]), "r"(a[1]), "r"(a[2]), "r"(a[3]), "r"(b[0]), "r"(b[1]));
}

// ---------------- prep: transpose W[k][ci][co] -> Wt[k][co][ci], rna round --
__global__ void __launch_bounds__(256) prep_w_kernel(const float* __restrict__ W,
                                                     float* __restrict__ Wt) {
    const int k = blockIdx.y;
    const int idx = blockIdx.x * 256 + threadIdx.x;  // over 16384
    const int ci = idx >> 7;
    const int co = idx & 127;
    float v = __ldg(&W[(long)k * 16384 + ci * 128 + co]);  // coalesced read
    Wt[(long)k * 16384 + co * 128 + ci] = rna_tf32(v);
}

// ---------------- one-shot rna rounding of features -------------------------
__global__ void __launch_bounds__(256) round_kernel(const float4* __restrict__ src,
                                                    float4* __restrict__ dst) {
    int i = blockIdx.x * 256 + threadIdx.x;
    if (i >= TOTAL4) return;
    float4 v = __ldg(&src[i]);
    v.x = rna_tf32(v.x); v.y = rna_tf32(v.y);
    v.z = rna_tf32(v.z); v.w = rna_tf32(v.w);
    dst[i] = v;
}

// ---------------- tf32 mma.sync pair-tile conv (cp.async double-buffered) ----
// Tile: 128 pairs x 128 outch x K=128, chunked K by 32, 2-stage pipeline.
// ATOMIC=false: center offset (k=13), plain stores (runs first, no zero pass).
// ATOMIC=true : 26 remaining offsets, red.global scatter-add.
template <bool ATOMIC>
__global__ void __launch_bounds__(256, 2) conv_mma_kernel(
    const float* __restrict__ feats, const float* __restrict__ Wt,
    const int* __restrict__ in_idx, const int* __restrict__ out_idx,
    float* __restrict__ out)
{
    extern __shared__ float dsm[];
    __shared__ int s_ii[TILE_M];
    __shared__ int s_oi[TILE_M];

    const int k = ATOMIC ? (blockIdx.y + (blockIdx.y >= 13 ? 1 : 0)) : 13;
    const long base = (long)blockIdx.x * TILE_M;
    const int* ik = in_idx + (long)k * N_SITES;
    if (ATOMIC && __ldg(&ik[base]) >= N_SITES) return;  // fully-padded chunk
    const int* ok = out_idx + (long)k * N_SITES;

    const int tid = threadIdx.x;
    const int wid = tid >> 5;
    const int lane = tid & 31;
    const int g = lane >> 2;       // group id (row within frag)
    const int tig = lane & 3;      // thread in group

    if (tid < TILE_M) {
        long p = base + tid;
        bool v = (p < N_SITES);
        s_ii[tid] = v ? __ldg(&ik[p]) : N_SITES;
        s_oi[tid] = v ? __ldg(&ok[p]) : N_SITES;
    }
    __syncthreads();

    const int warp_m = wid & 3;    // 0..3 -> 32-row band
    const int warp_n = wid >> 2;   // 0..1 -> 64-col band
    const int m0 = warp_m * 32;
    const int n0 = warp_n * 64;

    float acc[2][8][4];
    #pragma unroll
    for (int mf = 0; mf < 2; mf++)
        #pragma unroll
        for (int nf = 0; nf < 8; nf++)
            #pragma unroll
            for (int r = 0; r < 4; r++) acc[mf][nf][r] = 0.f;

    const float4* f4 = (const float4*)feats;
    const float4* w4 = (const float4*)(Wt + (long)k * 16384);
    const int r_st = tid >> 3;          // staging row base
    const int g4 = tid & 7;             // float4 granule within 32-float row

    const uint32_t dsm_base = smem_u32(dsm);

    // ---- stage chunk kc into pipeline buffer pb (0/1) via cp.async ----------
    auto stage = [&](int kc, int pb) {
        const uint32_t a_u32 = dsm_base + pb * (BUF_FLOATS * 4);
        const uint32_t b_u32 = a_u32 + TILE_M * LDS_STRIDE * 4;
        #pragma unroll
        for (int it = 0; it < 4; it++) {
            int r = r_st + it * 32;
            int ii = s_ii[r];
            bool v = (ii < N_SITES);
            const float4* src = f4 + (long)(v ? ii : 0) * 32 + kc * 8 + g4;
            cp_async16(a_u32 + r * (LDS_STRIDE * 4) + g4 * 16, src, v ? 16 : 0);
        }
        #pragma unroll
        for (int it = 0; it < 4; it++) {
            int r = r_st + it * 32;
            cp_async16(b_u32 + r * (LDS_STRIDE * 4) + g4 * 16,
                       w4 + r * 32 + kc * 8 + g4, 16);
        }
    };

    // ---- compute on pipeline buffer pb ---------------------------------------
    auto compute = [&](int pb) {
        const float* Asb = dsm + pb * BUF_FLOATS;
        const float* Bsb = Asb + TILE_M * LDS_STRIDE;
        #pragma unroll
        for (int ks = 0; ks < 4; ks++) {
            const int kk = ks * 8;
            uint32_t b[8][2];
            #pragma unroll
            for (int nf = 0; nf < 8; nf++) {
                const int n = n0 + nf * 8 + g;
                b[nf][0] = __float_as_uint(Bsb[n * LDS_STRIDE + kk + tig]);
                b[nf][1] = __float_as_uint(Bsb[n * LDS_STRIDE + kk + tig + 4]);
            }
            #pragma unroll
            for (int mf = 0; mf < 2; mf++) {
                const int row = m0 + mf * 16 + g;
                uint32_t a[4];
                a[0] = __float_as_uint(Asb[row * LDS_STRIDE + kk + tig]);
                a[1] = __float_as_uint(Asb[(row + 8) * LDS_STRIDE + kk + tig]);
                a[2] = __float_as_uint(Asb[row * LDS_STRIDE + kk + tig + 4]);
                a[3] = __float_as_uint(Asb[(row + 8) * LDS_STRIDE + kk + tig + 4]);
                #pragma unroll
                for (int nf = 0; nf < 8; nf++)
                    mma_tf32(acc[mf][nf], a, b[nf]);
            }
        }
    };

    // ---- 2-stage software pipeline over 4 K-chunks ---------------------------
    stage(0, 0);
    CP_COMMIT();
    #pragma unroll
    for (int kc = 0; kc < 4; kc++) {
        if (kc < 3) {
            stage(kc + 1, (kc + 1) & 1);
            CP_COMMIT();
            CP_WAIT(1);
        } else {
            CP_WAIT(0);
        }
        __syncthreads();
        compute(kc & 1);
        if (kc < 2) __syncthreads();  // before buf (kc&1) is restaged next iter
    }

    // ---- epilogue: rows -> out[oi] ------------------------------------------
    #pragma unroll
    for (int mf = 0; mf < 2; mf++) {
        const int r_lo = m0 + mf * 16 + g;
        const int oi_lo = s_oi[r_lo];
        const int oi_hi = s_oi[r_lo + 8];
        #pragma unroll
        for (int nf = 0; nf < 8; nf++) {
            const int col = n0 + nf * 8 + 2 * tig;
            if (oi_lo < N_SITES) {
                float* p = out + (long)oi_lo * C + col;
                if (ATOMIC) red_add2(p, acc[mf][nf][0], acc[mf][nf][1]);
                else        st2(p, acc[mf][nf][0], acc[mf][nf][1]);
            }
            if (oi_hi < N_SITES) {
                float* p = out + (long)oi_hi * C + col;
                if (ATOMIC) red_add2(p, acc[mf][nf][2], acc[mf][nf][3]);
                else        st2(p, acc[mf][nf][2], acc[mf][nf][3]);
            }
        }
    }
}

// ---------------- BN stats: per-block partial sum / sumsq per channel -------
__global__ void __launch_bounds__(256) bn_stats_kernel(const float* __restrict__ x) {
    const int b = blockIdx.x;
    const int r0 = b * STATS_ROWS;
    const int r1 = min(r0 + STATS_ROWS, N_SITES);
    const int c = threadIdx.x & 127;
    const int half = threadIdx.x >> 7;

    float s = 0.f, ss = 0.f;
    for (int r = r0 + half; r < r1; r += 2) {
        float v = __ldg(&x[(long)r * C + c]);
        s += v;
        ss += v * v;
    }
    __shared__ float sm[512];
    sm[threadIdx.x] = s;
    sm[256 + threadIdx.x] = ss;
    __syncthreads();
    if (half == 0) {
        g_part[((long)b * C + c) * 2 + 0] = s + sm[threadIdx.x + 128];
        g_part[((long)b * C + c) * 2 + 1] = ss + sm[256 + threadIdx.x + 128];
    }
}

// fixed-order finalize (4 workers per channel): deterministic mean/var
__global__ void __launch_bounds__(512) bn_final_kernel(const float* __restrict__ gamma,
                                                       const float* __restrict__ beta) {
    const int c = threadIdx.x & 127;
    const int w = threadIdx.x >> 7;  // 0..3
    float s = 0.f, ss = 0.f;
    for (int b = w; b < NB_STATS; b += 4) {
        s  += g_part[((long)b * C + c) * 2 + 0];
        ss += g_part[((long)b * C + c) * 2 + 1];
    }
    __shared__ float sm[1024];
    sm[threadIdx.x] = s;
    sm[512 + threadIdx.x] = ss;
    __syncthreads();
    if (w == 0) {
        #pragma unroll
        for (int j = 1; j < 4; j++) {
            s  += sm[j * 128 + c];
            ss += sm[512 + j * 128 + c];
        }
        const float inv_n = 1.f / (float)N_SITES;
        float m = s * inv_n;
        float v = ss * inv_n - m * m;
        float sc = gamma[c] * rsqrtf(v + EPS);
        g_scale[c] = sc;
        g_bias[c] = beta[c] - m * sc;
    }
}

// ---------------- elementwise: in-place BN + ReLU (+ rna for conv2 input) ---
__global__ void __launch_bounds__(256) bn_relu_kernel(float* __restrict__ x) {
    int i = blockIdx.x * 256 + threadIdx.x;
    if (i >= TOTAL4) return;
    float4 v = ((const float4*)x)[i];
    int c4 = i & 31;
    float4 s = ((const float4*)g_scale)[c4];
    float4 b = ((const float4*)g_bias)[c4];
    float4 o;
    o.x = rna_tf32(fmaxf(fmaf(v.x, s.x, b.x), 0.f));
    o.y = rna_tf32(fmaxf(fmaf(v.y, s.y, b.y), 0.f));
    o.z = rna_tf32(fmaxf(fmaf(v.z, s.z, b.z), 0.f));
    o.w = rna_tf32(fmaxf(fmaf(v.w, s.w, b.w), 0.f));
    ((float4*)x)[i] = o;
}

// ---------------- elementwise: BN + residual + ReLU -> output ---------------
__global__ void __launch_bounds__(256) apply_res_kernel(
    const float* __restrict__ x, const float* __restrict__ feats,
    float* __restrict__ out)
{
    int i = blockIdx.x * 256 + threadIdx.x;
    if (i >= TOTAL4) return;
    float4 v = ((const float4*)x)[i];
    float4 f = ((const float4*)feats)[i];
    int c4 = i & 31;
    float4 s = ((const float4*)g_scale)[c4];
    float4 b = ((const float4*)g_bias)[c4];
    float4 o;
    o.x = fmaxf(fmaf(v.x, s.x, b.x) + f.x, 0.f);
    o.y = fmaxf(fmaf(v.y, s.y, b.y) + f.y, 0.f);
    o.z = fmaxf(fmaf(v.z, s.z, b.z) + f.z, 0.f);
    o.w = fmaxf(fmaf(v.w, s.w, b.w) + f.w, 0.f);
    ((float4*)out)[i] = o;
}

// ---------------- launch ----------------------------------------------------
extern "C" void kernel_launch(void* const* d_in, const int* in_sizes, int n_in,
                              void* d_out, int out_size) {
    const float* feats  = (const float*)d_in[0];
    const float* W1     = (const float*)d_in[1];
    const float* gamma1 = (const float*)d_in[2];
    const float* beta1  = (const float*)d_in[3];
    const float* W2     = (const float*)d_in[4];
    const float* gamma2 = (const float*)d_in[5];
    const float* beta2  = (const float*)d_in[6];
    const int*   iidx   = (const int*)d_in[7];
    const int*   oidx   = (const int*)d_in[8];
    float* out = (float*)d_out;

    void *pb1, *pb2, *pw1, *pw2;
    cudaGetSymbolAddress(&pb1, g_buf1);
    cudaGetSymbolAddress(&pb2, g_buf2);
    cudaGetSymbolAddress(&pw1, g_wt1);
    cudaGetSymbolAddress(&pw2, g_wt2);
    float* buf1 = (float*)pb1;
    float* buf2 = (float*)pb2;
    float* wt1  = (float*)pw1;
    float* wt2  = (float*)pw2;

    cudaFuncSetAttribute(conv_mma_kernel<false>,
                         cudaFuncAttributeMaxDynamicSharedMemorySize, SMEM_DYN_BYTES);
    cudaFuncSetAttribute(conv_mma_kernel<true>,
                         cudaFuncAttributeMaxDynamicSharedMemorySize, SMEM_DYN_BYTES);

    const int EB = (TOTAL4 + 255) / 256;
    dim3 cgc(NCHUNK, 1);    // center store pass
    dim3 cga(NCHUNK, 26);   // atomic pass (26 non-center offsets)
    dim3 pg(64, NOFF);

    // weight transpose + tf32 rounding; rounded copy of features into buf2
    prep_w_kernel<<<pg, 256>>>(W1, wt1);
    prep_w_kernel<<<pg, 256>>>(W2, wt2);
    round_kernel<<<EB, 256>>>((const float4*)feats, (float4*)buf2);

    // conv1 (center store, then 26-offset scatter) -> BN1 -> ReLU(+rna)
    conv_mma_kernel<false><<<cgc, 256, SMEM_DYN_BYTES>>>(buf2, wt1, iidx, oidx, buf1);
    conv_mma_kernel<true ><<<cga, 256, SMEM_DYN_BYTES>>>(buf2, wt1, iidx, oidx, buf1);
    bn_stats_kernel<<<NB_STATS, 256>>>(buf1);
    bn_final_kernel<<<1, 512>>>(gamma1, beta1);
    bn_relu_kernel<<<EB, 256>>>(buf1);

    // conv2 -> BN2 -> +residual -> ReLU
    conv_mma_kernel<false><<<cgc, 256, SMEM_DYN_BYTES>>>(buf1, wt2, iidx, oidx, buf2);
    conv_mma_kernel<true ><<<cga, 256, SMEM_DYN_BYTES>>>(buf1, wt2, iidx, oidx, buf2);
    bn_stats_kernel<<<NB_STATS, 256>>>(buf2);
    bn_final_kernel<<<1, 512>>>(gamma2, beta2);
    apply_res_kernel<<<EB, 256>>>(buf2, feats, out);
}